// round 2
// baseline (speedup 1.0000x reference)
#include <cuda_runtime.h>
#include <math.h>

// Problem constants
#define T_STEPS 1024
#define BATCH   16
#define HID     512
#define NBLK    128   // persistent recurrence grid

typedef unsigned long long ull;

// ------------------------- static device scratch -------------------------
__device__ float g_gx[(size_t)BATCH * T_STEPS * 4 * HID];   // gate preactivations (input part)
__device__ float g_seq[(size_t)BATCH * T_STEPS * HID];      // layer-0 output sequence
__device__ float g_hT[2][HID / 2][32];                      // double-buffered h: [par][k>>1][b*2+(k&1)]
__device__ unsigned g_flag[NBLK * 32];                      // per-block step flags, 128B stride

// ------------------------- f32x2 helpers -------------------------
__device__ __forceinline__ ull ffma2(ull a, ull b, ull c) {
    ull d;
    asm("fma.rn.f32x2 %0, %1, %2, %3;" : "=l"(d) : "l"(a), "l"(b), "l"(c));
    return d;
}
__device__ __forceinline__ ull splat2(float a) {
    ull d;
    asm("mov.b64 %0, {%1, %1};" : "=l"(d) : "f"(a));
    return d;
}
__device__ __forceinline__ float2 unpack2(ull v) {
    float2 f;
    asm("mov.b64 {%0, %1}, %2;" : "=f"(f.x), "=f"(f.y) : "l"(v));
    return f;
}
__device__ __forceinline__ float sigm(float x) { return 1.0f / (1.0f + __expf(-x)); }

// ------------------------- init: reset flags + transpose h0 -------------------------
__global__ void init_state(const float* __restrict__ h0) {
    int i = blockIdx.x * blockDim.x + threadIdx.x;
    if (i < NBLK * 32) g_flag[i] = 0u;
    if (i < HID * BATCH) {
        int n = i >> 4, b = i & 15;
        g_hT[0][n >> 1][b * 2 + (n & 1)] = h0[b * HID + n];
    }
}

// ------------------------- big GEMM: gx = A @ W^T + bias -------------------------
// A: [M=16384][K=512] row-major, W: [N=2048][K=512] row-major, C = g_gx [M][N]
// 128x128 tile, 8x8 per thread, f32x2-packed along M (row pairs).
__global__ __launch_bounds__(256) void gemm_gates(const float* __restrict__ Aext, int useSeq,
                                                  const float* __restrict__ W,
                                                  const float* __restrict__ bias) {
    const float* A = useSeq ? g_seq : Aext;
    __shared__ float As[16][128];
    __shared__ float Bs[16][128];
    const int tid = threadIdx.x;
    const int tx = tid & 15, ty = tid >> 4;
    const int bn = blockIdx.x, bm = blockIdx.y;
    const float* Ab = A + (size_t)bm * 128 * 512;
    const float* Wb = W + (size_t)bn * 128 * 512;
    const int lr = tid >> 2;
    const int lc = (tid & 3) << 2;

    ull acc2[4][8];
#pragma unroll
    for (int i = 0; i < 4; i++)
#pragma unroll
        for (int j = 0; j < 8; j++) acc2[i][j] = 0ull;

    for (int k0 = 0; k0 < 512; k0 += 16) {
        float4 a0 = *(const float4*)(Ab + (size_t)lr * 512 + k0 + lc);
        float4 a1 = *(const float4*)(Ab + (size_t)(lr + 64) * 512 + k0 + lc);
        float4 w0 = *(const float4*)(Wb + (size_t)lr * 512 + k0 + lc);
        float4 w1 = *(const float4*)(Wb + (size_t)(lr + 64) * 512 + k0 + lc);
        __syncthreads();
        As[lc + 0][lr] = a0.x; As[lc + 1][lr] = a0.y; As[lc + 2][lr] = a0.z; As[lc + 3][lr] = a0.w;
        As[lc + 0][lr + 64] = a1.x; As[lc + 1][lr + 64] = a1.y; As[lc + 2][lr + 64] = a1.z; As[lc + 3][lr + 64] = a1.w;
        Bs[lc + 0][lr] = w0.x; Bs[lc + 1][lr] = w0.y; Bs[lc + 2][lr] = w0.z; Bs[lc + 3][lr] = w0.w;
        Bs[lc + 0][lr + 64] = w1.x; Bs[lc + 1][lr + 64] = w1.y; Bs[lc + 2][lr + 64] = w1.z; Bs[lc + 3][lr + 64] = w1.w;
        __syncthreads();
#pragma unroll
        for (int k = 0; k < 16; k++) {
            ulonglong2 av0 = *(const ulonglong2*)&As[k][ty * 8];
            ulonglong2 av1 = *(const ulonglong2*)&As[k][ty * 8 + 4];
            float4 bv0 = *(const float4*)&Bs[k][tx * 8];
            float4 bv1 = *(const float4*)&Bs[k][tx * 8 + 4];
            ull ap[4] = {av0.x, av0.y, av1.x, av1.y};
            ull bp[8] = {splat2(bv0.x), splat2(bv0.y), splat2(bv0.z), splat2(bv0.w),
                         splat2(bv1.x), splat2(bv1.y), splat2(bv1.z), splat2(bv1.w)};
#pragma unroll
            for (int i = 0; i < 4; i++)
#pragma unroll
                for (int j = 0; j < 8; j++) acc2[i][j] = ffma2(ap[i], bp[j], acc2[i][j]);
        }
    }

    const int ncol = bn * 128 + tx * 8;
    float bb[8];
#pragma unroll
    for (int j = 0; j < 8; j++) bb[j] = bias[ncol + j];
    float* Cb = g_gx + (size_t)(bm * 128 + ty * 8) * 2048 + ncol;
#pragma unroll
    for (int i2 = 0; i2 < 4; i2++) {
        float r0[8], r1[8];
#pragma unroll
        for (int j = 0; j < 8; j++) {
            float2 v = unpack2(acc2[i2][j]);
            r0[j] = v.x + bb[j];
            r1[j] = v.y + bb[j];
        }
        float* p0 = Cb + (size_t)(2 * i2) * 2048;
        float* p1 = p0 + 2048;
        *(float4*)(p0)     = make_float4(r0[0], r0[1], r0[2], r0[3]);
        *(float4*)(p0 + 4) = make_float4(r0[4], r0[5], r0[6], r0[7]);
        *(float4*)(p1)     = make_float4(r1[0], r1[1], r1[2], r1[3]);
        *(float4*)(p1 + 4) = make_float4(r1[4], r1[5], r1[6], r1[7]);
    }
}

// ------------------------- persistent recurrence -------------------------
// 128 blocks x 128 threads. Block bi owns hidden units n0=4*bi..+3 (16 gate rows).
// Thread (r = tid&15, s = tid>>4): gate-row r, K-slice [s*64, s*64+64).
// w_hh slice lives in REGISTERS (32 ull/thread); h staged to shared each step;
// inner-loop LDS are 16-lane broadcasts (2 unique lines/warp) -> FMA-bound.
__global__ __launch_bounds__(128, 1) void lstm_rec(const float* __restrict__ w_hh,
                                                   const float* __restrict__ b_hh,
                                                   const float* __restrict__ c0,
                                                   float* __restrict__ hfin, int storeSeq) {
    __shared__ float hs[256 * 32];       // 32 KB staged h: [k2][b*2+par]
    __shared__ float red[4 * 16 * 20];   // warp partials, padded rows
    __shared__ float gbuf[16 * 16];
    __shared__ float bsm[16];

    const int tid = threadIdx.x;
    const int bi = blockIdx.x;
    const int n0 = bi * 4;
    const int r = tid & 15;      // gate row within block
    const int s = tid >> 4;      // K slice (0..7)
    const int wrp = tid >> 5;

    // preload this thread's w_hh row-slice into registers (32 ull = 64 floats)
    const int gr = (r >> 2) * HID + n0 + (r & 3);   // global gate row
    ull wreg[32];
    {
        const float4* wrow = (const float4*)(w_hh + (size_t)gr * HID + s * 64);
#pragma unroll
        for (int i = 0; i < 16; i++) {
            float4 v = __ldg(wrow + i);
            ulonglong2 u = *(ulonglong2*)&v;
            wreg[2 * i] = u.x;
            wreg[2 * i + 1] = u.y;
        }
    }
    if (tid < 16) { int gi = tid >> 2, ui = tid & 3; bsm[tid] = b_hh[gi * HID + n0 + ui]; }

    float c = 0.f;
    if (tid < 64) { int u = tid >> 4, b = tid & 15; c = c0[b * HID + n0 + u]; }

    // indices for the gx/activation stage
    const int r0 = tid >> 4;     // 0..7
    const int b0 = tid & 15;
    const int r1 = r0 + 8;       // 8..15
    const int gxr0 = (r0 >> 2) * HID + n0 + (r0 & 3);
    const int gxr1 = (r1 >> 2) * HID + n0 + (r1 & 3);

    __syncthreads();

    for (int t = 0; t < T_STEPS; t++) {
        // prefetch gx for this step (independent of flags)
        float gx0 = __ldg(&g_gx[((size_t)b0 * T_STEPS + t) * 2048 + gxr0]);
        float gx1 = __ldg(&g_gx[((size_t)b0 * T_STEPS + t) * 2048 + gxr1]);

        if (t > 0) {
            // distributed flag barrier: each thread polls one producer's flag
            const unsigned tgt = (unsigned)t;
            const volatile unsigned* fp = &g_flag[tid * 32];
            bool ok = (*fp >= tgt);
            while (!__syncthreads_and(ok)) { ok = (*fp >= tgt); }
            __threadfence();
        }
        const int par = t & 1;

        // stage h (L1 bypass: written by other SMs)
        {
            const float4* hsrc = (const float4*)&g_hT[par][0][0];
            float4* hdst = (float4*)hs;
#pragma unroll
            for (int it = 0; it < 16; it++) {
                int idx = tid + it * 128;
                hdst[idx] = __ldcg(hsrc + idx);
            }
        }
        __syncthreads();

        // GEMV slice: row r, 16 batches, K in [s*64, s*64+64), f32x2 along K
        ull acc[16];
#pragma unroll
        for (int b = 0; b < 16; b++) acc[b] = 0ull;

        const ulonglong2* hbase = (const ulonglong2*)(hs + (s * 32) * 32);
#pragma unroll
        for (int kk = 0; kk < 32; kk++) {
            const ulonglong2* hp = hbase + kk * 8;
#pragma unroll
            for (int q = 0; q < 8; q++) {
                ulonglong2 hv = hp[q];
                acc[2 * q]     = ffma2(wreg[kk], hv.x, acc[2 * q]);
                acc[2 * q + 1] = ffma2(wreg[kk], hv.y, acc[2 * q + 1]);
            }
        }

        // horizontal: pair-sum, then fold the two K-slices within the warp
        float p[16];
#pragma unroll
        for (int b = 0; b < 16; b++) {
            float2 v = unpack2(acc[b]);
            p[b] = v.x + v.y;
        }
#pragma unroll
        for (int b = 0; b < 16; b++) p[b] += __shfl_xor_sync(0xffffffffu, p[b], 16);

        if (!(tid & 16)) {  // s even lanes hold the warp's partial for row r
            float* rp = &red[(wrp * 16 + r) * 20];
#pragma unroll
            for (int q = 0; q < 4; q++)
                *(float4*)&rp[q * 4] = make_float4(p[4 * q], p[4 * q + 1], p[4 * q + 2], p[4 * q + 3]);
        }
        __syncthreads();

        // combine 4 warp partials + gx + bias, apply activations
        {
            float s0 = red[(0 * 16 + r0) * 20 + b0] + red[(1 * 16 + r0) * 20 + b0] +
                       red[(2 * 16 + r0) * 20 + b0] + red[(3 * 16 + r0) * 20 + b0] + gx0 + bsm[r0];
            float s1 = red[(0 * 16 + r1) * 20 + b0] + red[(1 * 16 + r1) * 20 + b0] +
                       red[(2 * 16 + r1) * 20 + b0] + red[(3 * 16 + r1) * 20 + b0] + gx1 + bsm[r1];
            float a0 = sigm(s0);                           // rows 0..7: i, f
            float a1 = (r1 < 12) ? tanhf(s1) : sigm(s1);   // rows 8..11: g, 12..15: o
            gbuf[r0 * 16 + b0] = a0;
            gbuf[r1 * 16 + b0] = a1;
        }
        __syncthreads();

        if (tid < 64) {
            int u = tid >> 4, b = tid & 15;
            float iv = gbuf[(0 + u) * 16 + b];
            float fv = gbuf[(4 + u) * 16 + b];
            float gv = gbuf[(8 + u) * 16 + b];
            float ov = gbuf[(12 + u) * 16 + b];
            c = fv * c + iv * gv;
            float h = ov * tanhf(c);
            int n = n0 + u;
            g_hT[par ^ 1][n >> 1][b * 2 + (n & 1)] = h;
            if (storeSeq) g_seq[((size_t)b * T_STEPS + t) * HID + n] = h;
            if (t == T_STEPS - 1) hfin[b * HID + n] = h;
        }
        __threadfence();
        __syncthreads();
        if (tid == 0) *(volatile unsigned*)&g_flag[bi * 32] = (unsigned)(t + 1);
    }
}

// ------------------------- launch -------------------------
extern "C" void kernel_launch(void* const* d_in, const int* in_sizes, int n_in,
                              void* d_out, int out_size) {
    const float* x     = (const float*)d_in[0];
    const float* h0    = (const float*)d_in[1];
    const float* c0    = (const float*)d_in[2];
    const float* w_ih0 = (const float*)d_in[3];
    const float* w_hh0 = (const float*)d_in[4];
    const float* b_ih0 = (const float*)d_in[5];
    const float* b_hh0 = (const float*)d_in[6];
    const float* w_ih1 = (const float*)d_in[7];
    const float* w_hh1 = (const float*)d_in[8];
    const float* b_ih1 = (const float*)d_in[9];
    const float* b_hh1 = (const float*)d_in[10];
    float* out = (float*)d_out;

    dim3 ggrid(16, 128);  // N-tiles x M-tiles

    // layer 0
    init_state<<<32, 256>>>(h0);
    gemm_gates<<<ggrid, 256>>>(x, 0, w_ih0, b_ih0);
    lstm_rec<<<NBLK, 128>>>(w_hh0, b_hh0, c0, out, 1);

    // layer 1
    init_state<<<32, 256>>>(h0 + BATCH * HID);
    gemm_gates<<<ggrid, 256>>>(nullptr, 1, w_ih1, b_ih1);
    lstm_rec<<<NBLK, 128>>>(w_hh1, b_hh1, c0 + BATCH * HID, out + BATCH * HID, 0);
}